// round 1
// baseline (speedup 1.0000x reference)
#include <cuda_runtime.h>
#include <cstdint>

#define T_ODE   64
#define CDIM    256
#define VDIM    25
#define VPAD    28        // row padding: 28 floats = 112B, 16B-aligned rows
#define PE_LEN  89        // T_ODE + 25
#define NEG_SLOPE 0.01f

typedef unsigned long long ull;

// ---------------------------------------------------------------------------
// packed f32x2 helpers (sm_100+ PTX; ptxas never auto-generates FFMA2)
// ---------------------------------------------------------------------------
__device__ __forceinline__ ull fma2(ull a, ull b, ull c) {
    ull d;
    asm("fma.rn.f32x2 %0, %1, %2, %3;" : "=l"(d) : "l"(a), "l"(b), "l"(c));
    return d;
}
__device__ __forceinline__ ull dup2(float x) {
    ull d;
    asm("mov.b64 %0, {%1, %1};" : "=l"(d) : "f"(x));
    return d;
}
__device__ __forceinline__ void unpack2(ull a, float& x, float& y) {
    asm("mov.b64 {%0, %1}, %2;" : "=f"(x), "=f"(y) : "l"(a));
}

// ---------------------------------------------------------------------------
// PE table: pe[row][c], computed once per launch (double sin/cos: exact enough
// regardless of -use_fast_math; matches JAX fp32 PE to ~1e-6)
// ---------------------------------------------------------------------------
__device__ float g_pe[PE_LEN * CDIM];

__global__ void pe_init_kernel() {
    int idx = blockIdx.x * blockDim.x + threadIdx.x;
    if (idx >= PE_LEN * CDIM) return;
    int row = idx / CDIM, c = idx % CDIM;
    int p2 = (c >> 1) * 2;                                   // even index 2i
    float divf = expf((float)p2 * (-9.210340371976184f / 256.0f)); // -ln(1e4)/d
    double ang = (double)row * (double)divf;
    g_pe[idx] = (c & 1) ? (float)cos(ang) : (float)sin(ang);
}

// ---------------------------------------------------------------------------
// graph matmul: g[c][v] = sum_u h[c][u] * A[v][u]   (per-thread: rows tid, tid+128)
// packed over u-pairs; padding (u=25) is zero in both h and A.
// ---------------------------------------------------------------------------
__device__ __forceinline__ void gmul(const float* hs, float* gs, const float* As,
                                     int tid) {
#pragma unroll
    for (int r = 0; r < 2; r++) {
        int c = tid + r * 128;
        const ulonglong2* h2 = (const ulonglong2*)(hs + c * VPAD);
        ull hp[13];
#pragma unroll
        for (int j = 0; j < 7; j++) {
            ulonglong2 q = h2[j];
            hp[2 * j] = q.x;
            if (2 * j + 1 < 13) hp[2 * j + 1] = q.y;
        }
#pragma unroll 5
        for (int v = 0; v < VDIM; v++) {
            const ull* Ap = (const ull*)(As + v * 26);
            ull acc = 0ull;
#pragma unroll
            for (int j = 0; j < 13; j++) acc = fma2(hp[j], Ap[j], acc);
            float a, b;
            unpack2(acc, a, b);
            gs[c * VPAD + v] = a + b;
        }
        gs[c * VPAD + 25] = 0.f;
        gs[c * VPAD + 26] = 0.f;
        gs[c * VPAD + 27] = 0.f;
    }
}

// ---------------------------------------------------------------------------
// dense layer: dst[o][v] = act( sum_c W[o][c]*src[c][v] + bias[o] )
// 128 threads, each owns rows o=tid and o=tid+128 (13 f32x2 accumulators each).
// W staged in 8 chunks of 32 c-columns, transposed in SMEM at stride 257
// (odd stride -> conflict-free per-o reads and per-cc writes).
// ---------------------------------------------------------------------------
template <bool RELU>
__device__ __forceinline__ void layer(const float* src, float* dst,
                                      const float* __restrict__ W,
                                      const float* __restrict__ bias,
                                      float* ws, int tid) {
    ull acc0[13], acc1[13];
#pragma unroll
    for (int j = 0; j < 13; j++) { acc0[j] = 0ull; acc1[j] = 0ull; }

#pragma unroll 1
    for (int k = 0; k < 8; k++) {
        __syncthreads();   // previous chunk compute done before ws overwrite
        // stage W[:, 32k : 32k+32] -> ws[cc*257 + o]
#pragma unroll
        for (int q = 0; q < 16; q++) {
            int idx = tid + q * 128;
            int o = idx >> 3, j = idx & 7;
            float4 wv = *(const float4*)(W + o * CDIM + k * 32 + 4 * j);
            int cc = 4 * j;
            ws[(cc + 0) * 257 + o] = wv.x;
            ws[(cc + 1) * 257 + o] = wv.y;
            ws[(cc + 2) * 257 + o] = wv.z;
            ws[(cc + 3) * 257 + o] = wv.w;
        }
        __syncthreads();
#pragma unroll 2
        for (int cc = 0; cc < 32; cc++) {
            int c = k * 32 + cc;
            const ulonglong2* r2 = (const ulonglong2*)(src + c * VPAD);
            ull p[13];
#pragma unroll
            for (int j = 0; j < 7; j++) {
                ulonglong2 q = r2[j];
                p[2 * j] = q.x;
                if (2 * j + 1 < 13) p[2 * j + 1] = q.y;
            }
            ull wd0 = dup2(ws[cc * 257 + tid]);
            ull wd1 = dup2(ws[cc * 257 + tid + 128]);
#pragma unroll
            for (int j = 0; j < 13; j++) {
                acc0[j] = fma2(p[j], wd0, acc0[j]);
                acc1[j] = fma2(p[j], wd1, acc1[j]);
            }
        }
    }

    // epilogue: bias + (optional) LeakyReLU, store rows (skip pad lanes)
    float bb0 = bias[tid], bb1 = bias[tid + 128];
#pragma unroll
    for (int r = 0; r < 2; r++) {
        float bb = r ? bb1 : bb0;
        const ull* acc = r ? acc1 : acc0;
        float* d = dst + (tid + r * 128) * VPAD;
#pragma unroll
        for (int j = 0; j < 13; j++) {
            float x0, x1;
            unpack2(acc[j], x0, x1);
            x0 += bb; x1 += bb;
            if (RELU) {
                x0 = (x0 >= 0.f) ? x0 : NEG_SLOPE * x0;
                x1 = (x1 >= 0.f) ? x1 : NEG_SLOPE * x1;
            }
            d[2 * j] = x0;
            if (2 * j + 1 < VDIM) d[2 * j + 1] = x1;
        }
        d[25] = 0.f; d[26] = 0.f; d[27] = 0.f;
    }
}

// ---------------------------------------------------------------------------
// fused kernel: one CTA per sample n
// ---------------------------------------------------------------------------
__global__ void __launch_bounds__(128)
ode_kernel(const float* __restrict__ x,  const float* __restrict__ A,
           const float* __restrict__ w1, const float* __restrict__ b1,
           const float* __restrict__ w2, const float* __restrict__ b2,
           const float* __restrict__ wp, const float* __restrict__ bp,
           const int* __restrict__ tptr, float* __restrict__ out) {
    extern __shared__ float smem[];
    float* hs  = smem;                     // 256*28
    float* gs  = hs + CDIM * VPAD;         // 256*28
    float* ws  = gs + CDIM * VPAD;         // 32*257
    float* As  = ws + 32 * 257;            // 25*26
    float* pes = As + 25 * 26;             // 256

    const int tid = threadIdx.x;
    const int n   = blockIdx.x;
    const int row = (*tptr) + (n & (T_ODE - 1));

    // load A (zero-padded rows) + PE row
    for (int i = tid; i < VDIM * 26; i += 128) {
        int u = i % 26;
        As[i] = (u < VDIM) ? A[(i / 26) * VDIM + u] : 0.f;
    }
    for (int i = tid; i < CDIM; i += 128) pes[i] = g_pe[row * CDIM + i];
    __syncthreads();

    // h = x + pe (zero pads)
    const float* xn = x + (size_t)n * CDIM * VDIM;
    for (int i = tid; i < CDIM * VPAD; i += 128) {
        int c = i / VPAD, v = i % VPAD;
        hs[i] = (v < VDIM) ? xn[c * VDIM + v] + pes[c] : 0.f;
    }
    __syncthreads();

    gmul(hs, gs, As, tid);                 // g = A h
    __syncthreads();
    layer<true>(gs, hs, w1, b1, ws, tid);  // h = lrelu(w1 g + b1)
    __syncthreads();
    gmul(hs, gs, As, tid);                 // g = A h
    __syncthreads();
    layer<true>(gs, hs, w2, b2, ws, tid);  // h = lrelu(w2 g + b2)
    __syncthreads();
    layer<false>(hs, gs, wp, bp, ws, tid); // g = wp h + bp
    __syncthreads();

    // coalesced writeout
    float* on = out + (size_t)n * CDIM * VDIM;
    for (int i = tid; i < CDIM * VDIM; i += 128) {
        int c = i / VDIM, v = i % VDIM;
        on[i] = gs[c * VPAD + v];
    }
}

// ---------------------------------------------------------------------------
static const int SMEM_BYTES =
    (CDIM * VPAD * 2 + 32 * 257 + 25 * 26 + CDIM) * (int)sizeof(float); // 93864

extern "C" void kernel_launch(void* const* d_in, const int* in_sizes, int n_in,
                              void* d_out, int out_size) {
    const float* x  = (const float*)d_in[0];
    const float* A  = (const float*)d_in[1];
    const float* w1 = (const float*)d_in[2];
    const float* b1 = (const float*)d_in[3];
    const float* w2 = (const float*)d_in[4];
    const float* b2 = (const float*)d_in[5];
    const float* wp = (const float*)d_in[6];
    const float* bp = (const float*)d_in[7];
    const int*   t  = (const int*)d_in[8];
    float* out = (float*)d_out;

    const int B = in_sizes[0] / (CDIM * VDIM);   // 4096

    cudaFuncSetAttribute(ode_kernel,
                         cudaFuncAttributeMaxDynamicSharedMemorySize, SMEM_BYTES);

    pe_init_kernel<<<(PE_LEN * CDIM + 255) / 256, 256>>>();
    ode_kernel<<<B, 128, SMEM_BYTES>>>(x, A, w1, b1, w2, b2, wp, bp, t, out);
}

// round 4
// speedup vs baseline: 1.7993x; 1.7993x over previous
#include <cuda_runtime.h>
#include <cuda_bf16.h>
#include <cstdint>

typedef unsigned long long ull;

#define CDIM 256
#define VDIM 25
#define NSAMP 4
#define PE_LEN 89
#define NEG_SLOPE 0.01f

// ---- SMEM offsets from 1024-aligned base ----
#define H_OFF    0u          // 128 rows x 1024 B (Hh k<256 | Hl k>=256), also D
#define W_OFF    131072u     // 2 x 32 KB W chunk buffers
#define WBUF     32768u
#define AS2_OFF  196608u     // 25 x 13 packed f32x2 A rows = 2600 B
#define BIAS_OFF 199232u     // 3 x 256 f32
#define SMEM_DYN 203328u     // 202304 + 1024 align slack

// ---------------------------------------------------------------------------
// helpers
// ---------------------------------------------------------------------------
__device__ __forceinline__ uint32_t smem_u32(const void* p) {
    uint32_t a;
    asm("{ .reg .u64 t; cvta.to.shared.u64 t, %1; cvt.u32.u64 %0, t; }"
        : "=r"(a) : "l"(p));
    return a;
}
__device__ __forceinline__ ull fma2(ull a, ull b, ull c) {
    ull d;
    asm("fma.rn.f32x2 %0, %1, %2, %3;" : "=l"(d) : "l"(a), "l"(b), "l"(c));
    return d;
}
__device__ __forceinline__ void cpasync16(uint32_t dst, const void* src) {
    asm volatile("cp.async.cg.shared.global [%0], [%1], 16;" :: "r"(dst), "l"(src));
}
#define CP_COMMIT() asm volatile("cp.async.commit_group;" ::: "memory")
#define CP_WAIT1()  asm volatile("cp.async.wait_group 1;" ::: "memory")
#define CP_WAIT0()  asm volatile("cp.async.wait_group 0;" ::: "memory")

__device__ __forceinline__ void ldsm4(uint32_t* r, uint32_t a) {
    asm volatile("ldmatrix.sync.aligned.m8n8.x4.shared.b16 {%0,%1,%2,%3}, [%4];"
        : "=r"(r[0]), "=r"(r[1]), "=r"(r[2]), "=r"(r[3]) : "r"(a));
}
__device__ __forceinline__ void mma_bf16(float* d, const uint32_t* a,
                                         const uint32_t* b) {
    asm volatile(
        "mma.sync.aligned.m16n8k16.row.col.f32.bf16.bf16.f32 "
        "{%0,%1,%2,%3}, {%4,%5,%6,%7}, {%8,%9}, {%0,%1,%2,%3};"
        : "+f"(d[0]), "+f"(d[1]), "+f"(d[2]), "+f"(d[3])
        : "r"(a[0]), "r"(a[1]), "r"(a[2]), "r"(a[3]), "r"(b[0]), "r"(b[1]));
}
__device__ __forceinline__ void sts_f32(uint32_t a, float v) {
    asm volatile("st.shared.f32 [%0], %1;" :: "r"(a), "f"(v));
}
__device__ __forceinline__ float lds_f32(uint32_t a) {
    float v; asm volatile("ld.shared.f32 %0, [%1];" : "=f"(v) : "r"(a)); return v;
}
__device__ __forceinline__ void sts_u16(uint32_t a, uint16_t v) {
    asm volatile("st.shared.u16 [%0], %1;" :: "r"(a), "h"(v));
}
__device__ __forceinline__ ull lds_u64(uint32_t a) {
    ull v; asm volatile("ld.shared.b64 %0, [%1];" : "=l"(v) : "r"(a)); return v;
}
__device__ __forceinline__ void sts_u64(uint32_t a, ull v) {
    asm volatile("st.shared.b64 [%0], %1;" :: "r"(a), "l"(v));
}
__device__ __forceinline__ void sts_z16(uint32_t a) {
    asm volatile("st.shared.v4.b32 [%0], {%1,%1,%1,%1};" :: "r"(a), "r"(0u));
}

// H tile: [n row (0..127)] x [k (0..511)] bf16, 1024 B rows, XOR-swizzled 16B units
__device__ __forceinline__ uint32_t h_addr(uint32_t hb, int n, int k) {
    return hb + n * 1024 + ((((k >> 3) ^ (n & 7)) << 4) | ((k & 7) << 1));
}
// W chunk buffer: [o (0..255)] x [k (0..63)] bf16, 128 B rows, swizzled
__device__ __forceinline__ uint32_t w_addr(uint32_t wb, int o, int k) {
    return wb + o * 128 + ((((k >> 3) ^ (o & 7)) << 4) | ((k & 7) << 1));
}
// D (fp32) overlay in H region: [n][o], XOR-swizzled
__device__ __forceinline__ uint32_t d_addr(uint32_t hb, int n, int o) {
    return hb + n * 1024 + ((o ^ ((n & 7) << 2)) << 2);
}

__device__ __forceinline__ void split2(float v, uint16_t& hi, uint16_t& lo) {
    __nv_bfloat16 h = __float2bfloat16(v);
    __nv_bfloat16 l = __float2bfloat16(v - __bfloat162float(h));
    hi = __bfloat16_as_ushort(h);
    lo = __bfloat16_as_ushort(l);
}

// ---------------------------------------------------------------------------
// device globals + prep kernels
// ---------------------------------------------------------------------------
__device__ float g_pe[PE_LEN * CDIM];
__device__ __nv_bfloat16 g_ws[3 * 2 * 256 * 256];   // [layer][part(hi/lo)][o][c]

__global__ void pe_init_kernel() {
    int idx = blockIdx.x * blockDim.x + threadIdx.x;
    if (idx >= PE_LEN * CDIM) return;
    int row = idx / CDIM, c = idx % CDIM;
    int p2 = (c >> 1) * 2;
    float divf = expf((float)p2 * (-9.210340371976184f / 256.0f));
    double ang = (double)row * (double)divf;
    g_pe[idx] = (c & 1) ? (float)cos(ang) : (float)sin(ang);
}

__global__ void w_split_kernel(const float* __restrict__ w1,
                               const float* __restrict__ w2,
                               const float* __restrict__ wp) {
    int i = blockIdx.x * blockDim.x + threadIdx.x;
    if (i >= 3 * CDIM * CDIM) return;
    int l = i / (CDIM * CDIM), rem = i % (CDIM * CDIM);
    const float* w = (l == 0) ? w1 : ((l == 1) ? w2 : wp);
    float v = w[rem];
    __nv_bfloat16 h = __float2bfloat16(v);
    __nv_bfloat16 lo = __float2bfloat16(v - __bfloat162float(h));
    g_ws[((size_t)(l * 2 + 0) * 256) * 256 + rem] = h;
    g_ws[((size_t)(l * 2 + 1) * 256) * 256 + rem] = lo;
}

// stage W virtual chunk vv (layer=vv>>3, part=vv&1, chunk=(vv>>1)&3) -> buf
__device__ __forceinline__ void stage_w(uint32_t wb, int vv, int tid) {
    const __nv_bfloat16* src = g_ws
        + ((size_t)((vv >> 3) * 2 + (vv & 1)) * 256) * 256
        + (size_t)(((vv >> 1) & 3) * 64);
#pragma unroll
    for (int q = 0; q < 8; q++) {
        int t = tid + q * 256;
        int o = t >> 3, k8 = (t & 7) << 3;
        cpasync16(w_addr(wb, o, k8), src + (size_t)o * 256 + k8);
    }
}

// ---------------------------------------------------------------------------
// main kernel: 1 CTA = 4 samples; 3 HMMA GEMM layers with fused A/bias/lrelu
// ---------------------------------------------------------------------------
__global__ void __launch_bounds__(256, 1)
ode_main(const float* __restrict__ x, const float* __restrict__ A,
         const float* __restrict__ b1, const float* __restrict__ b2,
         const float* __restrict__ bp, const int* __restrict__ tptr,
         float* __restrict__ out) {
    extern __shared__ char raw[];
    uint32_t rawu = smem_u32(raw);
    uint32_t base = (rawu + 1023u) & ~1023u;

    const int tid = threadIdx.x, lane = tid & 31, wid = tid >> 5;
    const int blk = blockIdx.x;
    const uint32_t hb = base + H_OFF;
    const int ob = (wid >> 1) * 64;     // warp m-tile origin
    const int nb = (wid & 1) * 64;      // warp n-tile origin

    // kick off W prefetch for vchunks 0, 1 immediately
    stage_w(base + W_OFF, 0, tid);          CP_COMMIT();
    stage_w(base + W_OFF + WBUF, 1, tid);   CP_COMMIT();

    // stage A (packed f32x2 rows) + biases
    for (int i = tid; i < VDIM * 13; i += 256) {
        int v = i / 13, j = i % 13, u0 = 2 * j, u1 = 2 * j + 1;
        float f0 = A[v * VDIM + u0];
        float f1 = (u1 < VDIM) ? A[v * VDIM + u1] : 0.f;
        ull p = (ull)__float_as_uint(f0) | ((ull)__float_as_uint(f1) << 32);
        sts_u64(base + AS2_OFF + i * 8, p);
    }
    for (int i = tid; i < 768; i += 256) {
        float bv = (i < 256) ? b1[i] : ((i < 512) ? b2[i - 256] : bp[i - 512]);
        sts_f32(base + BIAS_OFF + i * 4, bv);
    }

    // build H = split(x + pe): Hh at k=c, Hl at k=256+c; rows n = s*32+v
    const int t0 = *tptr;
    for (int i = tid; i < NSAMP * CDIM * VDIM; i += 256) {
        int s = i / (CDIM * VDIM);
        int rem = i - s * (CDIM * VDIM);
        int c = rem / VDIM, v = rem - c * VDIM;
        int n = blk * NSAMP + s;
        float val = x[(size_t)n * (CDIM * VDIM) + rem]
                  + g_pe[(t0 + (n & 63)) * CDIM + c];
        uint16_t hi, lo;
        split2(val, hi, lo);
        int nr = s * 32 + v;
        sts_u16(h_addr(hb, nr, c), hi);
        sts_u16(h_addr(hb, nr, 256 + c), lo);
    }
    // zero pad rows v=25..31 (28 rows x 1024 B)
    for (int i = tid; i < 28 * 64; i += 256) {
        int r = i >> 6;
        int s = r / 7, v = 25 + (r % 7);
        sts_z16(hb + (s * 32 + v) * 1024 + (i & 63) * 16);
    }
    __syncthreads();

    float acc[4][8][4];
#pragma unroll
    for (int i = 0; i < 4; i++)
#pragma unroll
        for (int j = 0; j < 8; j++)
#pragma unroll
            for (int e = 0; e < 4; e++) acc[i][j][e] = 0.f;

    // 24 virtual chunks: 3 layers x (4 chunks x {Wh, Wl})
#pragma unroll 1
    for (int vv = 0; vv < 24; vv++) {
        if (vv < 23) CP_WAIT1(); else CP_WAIT0();
        __syncthreads();
        const uint32_t wb = base + W_OFF + (uint32_t)(vv & 1) * WBUF;
        const int chunk = (vv >> 1) & 3;
        const int part = vv & 1;          // 0=Wh (x Hh, x Hl), 1=Wl (x Hh)

#pragma unroll
        for (int kk = 0; kk < 4; kk++) {
            uint32_t a[4][4];
            {
                int sel = lane >> 3;
                int o = ob + (lane & 7) + ((sel & 1) << 3);
                int k = kk * 16 + ((sel >> 1) << 3);
#pragma unroll
                for (int i = 0; i < 4; i++)
                    ldsm4(a[i], w_addr(wb, o + i * 16, k));
            }
#pragma unroll
            for (int tgt = 0; tgt < 2; tgt++) {
                if (part && tgt) break;                      // Wl: Hh only
                int kh = (part ? 0 : tgt * 256) + chunk * 64 + kk * 16;
                uint32_t b[8][2];
                {
                    int sel = lane >> 3;
                    int n0 = nb + (lane & 7) + ((sel >> 1) << 3);
                    int k = kh + ((sel & 1) << 3);
#pragma unroll
                    for (int jj = 0; jj < 4; jj++) {
                        uint32_t r[4];
                        ldsm4(r, h_addr(hb, n0 + jj * 16, k));
                        b[2 * jj][0] = r[0]; b[2 * jj][1] = r[1];
                        b[2 * jj + 1][0] = r[2]; b[2 * jj + 1][1] = r[3];
                    }
                }
#pragma unroll
                for (int i = 0; i < 4; i++)
#pragma unroll
                    for (int j = 0; j < 8; j++)
                        mma_bf16(acc[i][j], a[i], b[j]);
            }
        }
        __syncthreads();                 // all warps done reading buf[vv&1]
        if (vv + 2 < 24) {
            stage_w(base + W_OFF + (uint32_t)(vv & 1) * WBUF, vv + 2, tid);
            CP_COMMIT();
        }

        if ((vv & 7) == 7) {             // ---- layer epilogue ----
            const int l = vv >> 3;
            if (l < 2) {
                // 1) acc -> D (fp32 overlay on H region)
#pragma unroll
                for (int i = 0; i < 4; i++) {
                    int o = ob + i * 16 + (lane >> 2);
#pragma unroll
                    for (int j = 0; j < 8; j++) {
                        int n = nb + j * 8 + 2 * (lane & 3);
                        sts_f32(d_addr(hb, n, o),     acc[i][j][0]);
                        sts_f32(d_addr(hb, n + 1, o), acc[i][j][1]);
                        sts_f32(d_addr(hb, n, o + 8),     acc[i][j][2]);
                        sts_f32(d_addr(hb, n + 1, o + 8), acc[i][j][3]);
                    }
                }
                __syncthreads();
                // 2) read all D rows this thread needs (o = tid)
                ull du[NSAMP][13];
#pragma unroll
                for (int s = 0; s < NSAMP; s++) {
                    float tv[26];
                    tv[25] = 0.f;
#pragma unroll
                    for (int u = 0; u < 25; u++)
                        tv[u] = lds_f32(d_addr(hb, s * 32 + u, tid));
#pragma unroll
                    for (int j = 0; j < 13; j++)
                        du[s][j] = (ull)__float_as_uint(tv[2 * j])
                                 | ((ull)__float_as_uint(tv[2 * j + 1]) << 32);
                }
                __syncthreads();
                // 3) A^T mult + bias + lrelu + re-split into H
                float bb = lds_f32(base + BIAS_OFF + (l * 256 + tid) * 4);
#pragma unroll 1
                for (int s = 0; s < NSAMP; s++) {
#pragma unroll 5
                    for (int v = 0; v < VDIM; v++) {
                        ull accv = 0ull;
#pragma unroll
                        for (int j = 0; j < 13; j++)
                            accv = fma2(du[s][j],
                                        lds_u64(base + AS2_OFF + (v * 13 + j) * 8),
                                        accv);
                        float a0, a1;
                        asm("mov.b64 {%0,%1}, %2;" : "=f"(a0), "=f"(a1) : "l"(accv));
                        float r = a0 + a1 + bb;
                        r = (r >= 0.f) ? r : NEG_SLOPE * r;
                        uint16_t hi, lo;
                        split2(r, hi, lo);
                        int nr = s * 32 + v;
                        sts_u16(h_addr(hb, nr, tid), hi);
                        sts_u16(h_addr(hb, nr, 256 + tid), lo);
                    }
                }
                __syncthreads();
            } else {
                // final layer: bias + direct gmem store from fragments
#pragma unroll
                for (int i = 0; i < 4; i++) {
                    int o0 = ob + i * 16 + (lane >> 2);
                    float bb0 = lds_f32(base + BIAS_OFF + (512 + o0) * 4);
                    float bb1 = lds_f32(base + BIAS_OFF + (512 + o0 + 8) * 4);
#pragma unroll
                    for (int j = 0; j < 8; j++) {
                        int n = nb + j * 8 + 2 * (lane & 3);
                        int s = n >> 5, v = n & 31;
                        size_t o_base = ((size_t)(blk * NSAMP + s)) * (CDIM * VDIM);
                        if (v < VDIM) {
                            out[o_base + o0 * VDIM + v] = acc[i][j][0] + bb0;
                            out[o_base + (o0 + 8) * VDIM + v] = acc[i][j][2] + bb1;
                        }
                        if (v + 1 < VDIM) {
                            out[o_base + o0 * VDIM + v + 1] = acc[i][j][1] + bb0;
                            out[o_base + (o0 + 8) * VDIM + v + 1] = acc[i][j][3] + bb1;
                        }
                    }
                }
            }
            // reset accumulators for next layer
#pragma unroll
            for (int i = 0; i < 4; i++)
#pragma unroll
                for (int j = 0; j < 8; j++)
#pragma unroll
                    for (int e = 0; e < 4; e++) acc[i][j][e] = 0.f;
        }
    }
}

// ---------------------------------------------------------------------------
extern "C" void kernel_launch(void* const* d_in, const int* in_sizes, int n_in,
                              void* d_out, int out_size) {
    const float* x  = (const float*)d_in[0];
    const float* A  = (const float*)d_in[1];
    const float* w1 = (const float*)d_in[2];
    const float* b1 = (const float*)d_in[3];
    const float* w2 = (const float*)d_in[4];
    const float* b2 = (const float*)d_in[5];
    const float* wp = (const float*)d_in[6];
    const float* bp = (const float*)d_in[7];
    const int*   t  = (const int*)d_in[8];
    float* out = (float*)d_out;

    const int B = in_sizes[0] / (CDIM * VDIM);   // 4096

    cudaFuncSetAttribute(ode_main, cudaFuncAttributeMaxDynamicSharedMemorySize,
                         SMEM_DYN);

    pe_init_kernel<<<(PE_LEN * CDIM + 255) / 256, 256>>>();
    w_split_kernel<<<(3 * CDIM * CDIM + 255) / 256, 256>>>(w1, w2, wp);
    ode_main<<<B / NSAMP, 256, SMEM_DYN>>>(x, A, b1, b2, bp, t, out);
}

// round 5
// speedup vs baseline: 2.2963x; 1.2762x over previous
#include <cuda_runtime.h>
#include <cuda_bf16.h>
#include <cstdint>

typedef unsigned long long ull;

#define CDIM 256
#define VDIM 25
#define NSAMP 4
#define PE_LEN 89
#define NEG_SLOPE 0.01f

// ---- SMEM offsets from 1024-aligned base ----
#define H_OFF    0u          // 128 rows x 1024 B (Hh k<256 | Hl k>=256), also D
#define W_OFF    131072u     // 2 x 32 KB W chunk buffers
#define WBUF     32768u
#define AS2_OFF  196608u     // 25 x 13 packed f32x2 A rows = 2600 B
#define BIAS_OFF 199232u     // 3 x 256 f32
#define SMEM_DYN 203328u

// ---------------------------------------------------------------------------
// helpers
// ---------------------------------------------------------------------------
__device__ __forceinline__ uint32_t smem_u32(const void* p) {
    uint32_t a;
    asm("{ .reg .u64 t; cvta.to.shared.u64 t, %1; cvt.u32.u64 %0, t; }"
        : "=r"(a) : "l"(p));
    return a;
}
__device__ __forceinline__ ull fma2(ull a, ull b, ull c) {
    ull d;
    asm("fma.rn.f32x2 %0, %1, %2, %3;" : "=l"(d) : "l"(a), "l"(b), "l"(c));
    return d;
}
__device__ __forceinline__ void cpasync16(uint32_t dst, const void* src) {
    asm volatile("cp.async.cg.shared.global [%0], [%1], 16;" :: "r"(dst), "l"(src));
}
#define CP_COMMIT() asm volatile("cp.async.commit_group;" ::: "memory")
#define CP_WAIT1()  asm volatile("cp.async.wait_group 1;" ::: "memory")
#define CP_WAIT0()  asm volatile("cp.async.wait_group 0;" ::: "memory")

__device__ __forceinline__ void ldsm4(uint32_t* r, uint32_t a) {
    asm volatile("ldmatrix.sync.aligned.m8n8.x4.shared.b16 {%0,%1,%2,%3}, [%4];"
        : "=r"(r[0]), "=r"(r[1]), "=r"(r[2]), "=r"(r[3]) : "r"(a));
}
__device__ __forceinline__ void mma_bf16(float* d, const uint32_t* a,
                                         const uint32_t* b) {
    asm volatile(
        "mma.sync.aligned.m16n8k16.row.col.f32.bf16.bf16.f32 "
        "{%0,%1,%2,%3}, {%4,%5,%6,%7}, {%8,%9}, {%0,%1,%2,%3};"
        : "+f"(d[0]), "+f"(d[1]), "+f"(d[2]), "+f"(d[3])
        : "r"(a[0]), "r"(a[1]), "r"(a[2]), "r"(a[3]), "r"(b[0]), "r"(b[1]));
}
__device__ __forceinline__ void sts_f32(uint32_t a, float v) {
    asm volatile("st.shared.f32 [%0], %1;" :: "r"(a), "f"(v));
}
__device__ __forceinline__ float lds_f32(uint32_t a) {
    float v; asm volatile("ld.shared.f32 %0, [%1];" : "=f"(v) : "r"(a)); return v;
}
__device__ __forceinline__ void sts_u16(uint32_t a, uint16_t v) {
    asm volatile("st.shared.u16 [%0], %1;" :: "r"(a), "h"(v));
}
__device__ __forceinline__ ull lds_u64(uint32_t a) {
    ull v; asm volatile("ld.shared.b64 %0, [%1];" : "=l"(v) : "r"(a)); return v;
}
__device__ __forceinline__ void sts_u64(uint32_t a, ull v) {
    asm volatile("st.shared.b64 [%0], %1;" :: "r"(a), "l"(v));
}
__device__ __forceinline__ void sts_z16(uint32_t a) {
    asm volatile("st.shared.v4.b32 [%0], {%1,%1,%1,%1};" :: "r"(a), "r"(0u));
}

// H tile: [n row (0..127)] x [k (0..511)] bf16, 1024 B rows, XOR-swizzled
__device__ __forceinline__ uint32_t h_addr(uint32_t hb, int n, int k) {
    return hb + n * 1024 + ((((k >> 3) ^ (n & 7)) << 4) | ((k & 7) << 1));
}
// W chunk buffer: [o (0..255)] x [k (0..63)] bf16, 128 B rows, swizzled
__device__ __forceinline__ uint32_t w_addr(uint32_t wb, int o, int k) {
    return wb + o * 128 + ((((k >> 3) ^ (o & 7)) << 4) | ((k & 7) << 1));
}
// D (fp32) overlay in H region: [n][o], XOR-swizzled
__device__ __forceinline__ uint32_t d_addr(uint32_t hb, int n, int o) {
    return hb + n * 1024 + ((o ^ ((n & 7) << 2)) << 2);
}

__device__ __forceinline__ void split2(float v, uint16_t& hi, uint16_t& lo) {
    __nv_bfloat16 h = __float2bfloat16(v);
    __nv_bfloat16 l = __float2bfloat16(v - __bfloat162float(h));
    hi = __bfloat16_as_ushort(h);
    lo = __bfloat16_as_ushort(l);
}

// ---------------------------------------------------------------------------
// device globals + prep kernels
// ---------------------------------------------------------------------------
__device__ float g_pe[PE_LEN * CDIM];
__device__ __nv_bfloat16 g_ws[3 * 2 * 256 * 256];   // [layer][part(hi/lo)][o][c]

__global__ void pe_init_kernel() {
    int idx = blockIdx.x * blockDim.x + threadIdx.x;
    if (idx >= PE_LEN * CDIM) return;
    int row = idx / CDIM, c = idx % CDIM;
    int p2 = (c >> 1) * 2;
    float divf = expf((float)p2 * (-9.210340371976184f / 256.0f));
    double ang = (double)row * (double)divf;
    g_pe[idx] = (c & 1) ? (float)cos(ang) : (float)sin(ang);
}

__global__ void w_split_kernel(const float* __restrict__ w1,
                               const float* __restrict__ w2,
                               const float* __restrict__ wp) {
    int i = blockIdx.x * blockDim.x + threadIdx.x;
    if (i >= 3 * CDIM * CDIM) return;
    int l = i / (CDIM * CDIM), rem = i % (CDIM * CDIM);
    const float* w = (l == 0) ? w1 : ((l == 1) ? w2 : wp);
    float v = w[rem];
    __nv_bfloat16 h = __float2bfloat16(v);
    __nv_bfloat16 lo = __float2bfloat16(v - __bfloat162float(h));
    g_ws[((size_t)(l * 2 + 0) * 256) * 256 + rem] = h;
    g_ws[((size_t)(l * 2 + 1) * 256) * 256 + rem] = lo;
}

// stage W virtual chunk vv (layer=vv>>3, part=vv&1, chunk=(vv>>1)&3) -> buf
__device__ __forceinline__ void stage_w(uint32_t wb, int vv, int tid) {
    const __nv_bfloat16* src = g_ws
        + ((size_t)((vv >> 3) * 2 + (vv & 1)) * 256) * 256
        + (size_t)(((vv >> 1) & 3) * 64);
#pragma unroll
    for (int q = 0; q < 4; q++) {
        int t = tid + q * 512;
        int o = t >> 3, k8 = (t & 7) << 3;
        cpasync16(w_addr(wb, o, k8), src + (size_t)o * 256 + k8);
    }
}

// ---------------------------------------------------------------------------
// main kernel: 1 CTA = 4 samples, 512 threads (16 warps, 4x4 warp grid)
// ---------------------------------------------------------------------------
__global__ void __launch_bounds__(512, 1)
ode_main(const float* __restrict__ x, const float* __restrict__ A,
         const float* __restrict__ b1, const float* __restrict__ b2,
         const float* __restrict__ bp, const int* __restrict__ tptr,
         float* __restrict__ out) {
    extern __shared__ char raw[];
    uint32_t rawu = smem_u32(raw);
    uint32_t base = (rawu + 1023u) & ~1023u;

    const int tid = threadIdx.x, lane = tid & 31, wid = tid >> 5;
    const int blk = blockIdx.x;
    const uint32_t hb = base + H_OFF;
    const int ob = (wid >> 2) * 64;     // warp m-tile origin (o)
    const int nb = (wid & 3) * 32;      // warp n-tile origin (rows)

    // kick off W prefetch for vchunks 0, 1 immediately
    stage_w(base + W_OFF, 0, tid);          CP_COMMIT();
    stage_w(base + W_OFF + WBUF, 1, tid);   CP_COMMIT();

    // stage A (packed f32x2 rows) + biases
    for (int i = tid; i < VDIM * 13; i += 512) {
        int v = i / 13, j = i % 13, u0 = 2 * j, u1 = 2 * j + 1;
        float f0 = A[v * VDIM + u0];
        float f1 = (u1 < VDIM) ? A[v * VDIM + u1] : 0.f;
        ull p = (ull)__float_as_uint(f0) | ((ull)__float_as_uint(f1) << 32);
        sts_u64(base + AS2_OFF + i * 8, p);
    }
    for (int i = tid; i < 768; i += 512) {
        float bv = (i < 256) ? b1[i] : ((i < 512) ? b2[i - 256] : bp[i - 512]);
        sts_f32(base + BIAS_OFF + i * 4, bv);
    }

    // build H = split(x + pe): Hh at k=c, Hl at k=256+c; rows n = s*32+v
    const int t0 = *tptr;
    for (int i = tid; i < NSAMP * CDIM * VDIM; i += 512) {
        int s = i / (CDIM * VDIM);
        int rem = i - s * (CDIM * VDIM);
        int c = rem / VDIM, v = rem - c * VDIM;
        int n = blk * NSAMP + s;
        float val = x[(size_t)n * (CDIM * VDIM) + rem]
                  + g_pe[(t0 + (n & 63)) * CDIM + c];
        uint16_t hi, lo;
        split2(val, hi, lo);
        int nr = s * 32 + v;
        sts_u16(h_addr(hb, nr, c), hi);
        sts_u16(h_addr(hb, nr, 256 + c), lo);
    }
    // zero pad rows v=25..31 (28 rows x 1024 B)
    for (int i = tid; i < 28 * 64; i += 512) {
        int r = i >> 6;
        int s = r / 7, v = 25 + (r % 7);
        sts_z16(hb + (s * 32 + v) * 1024 + (i & 63) * 16);
    }
    __syncthreads();

    float acc[4][4][4];
#pragma unroll
    for (int i = 0; i < 4; i++)
#pragma unroll
        for (int j = 0; j < 4; j++)
#pragma unroll
            for (int e = 0; e < 4; e++) acc[i][j][e] = 0.f;

    // 24 virtual chunks: 3 layers x (4 chunks x {Wh, Wl})
#pragma unroll 1
    for (int vv = 0; vv < 24; vv++) {
        if (vv < 23) CP_WAIT1(); else CP_WAIT0();
        __syncthreads();
        const uint32_t wb = base + W_OFF + (uint32_t)(vv & 1) * WBUF;
        const int chunk = (vv >> 1) & 3;
        const int part = vv & 1;          // 0=Wh (x Hh, x Hl), 1=Wl (x Hh)

#pragma unroll
        for (int kk = 0; kk < 4; kk++) {
            uint32_t a[4][4];
            {
                int sel = lane >> 3;
                int o = ob + (lane & 7) + ((sel & 1) << 3);
                int k = kk * 16 + ((sel >> 1) << 3);
#pragma unroll
                for (int i = 0; i < 4; i++)
                    ldsm4(a[i], w_addr(wb, o + i * 16, k));
            }
#pragma unroll
            for (int tgt = 0; tgt < 2; tgt++) {
                if (part && tgt) break;                      // Wl: Hh only
                int kh = (part ? 0 : tgt * 256) + chunk * 64 + kk * 16;
                uint32_t b[4][2];
                {
                    int sel = lane >> 3;
                    int n0 = nb + (lane & 7) + ((sel >> 1) << 3);
                    int k = kh + ((sel & 1) << 3);
#pragma unroll
                    for (int jj = 0; jj < 2; jj++) {
                        uint32_t r[4];
                        ldsm4(r, h_addr(hb, n0 + jj * 16, k));
                        b[2 * jj][0] = r[0]; b[2 * jj][1] = r[1];
                        b[2 * jj + 1][0] = r[2]; b[2 * jj + 1][1] = r[3];
                    }
                }
#pragma unroll
                for (int i = 0; i < 4; i++)
#pragma unroll
                    for (int j = 0; j < 4; j++)
                        mma_bf16(acc[i][j], a[i], b[j]);
            }
        }
        __syncthreads();                 // all warps done reading buf[vv&1]
        if (vv + 2 < 24) {
            stage_w(base + W_OFF + (uint32_t)(vv & 1) * WBUF, vv + 2, tid);
            CP_COMMIT();
        }

        if ((vv & 7) == 7) {             // ---- layer epilogue ----
            const int l = vv >> 3;
            if (l < 2) {
                // 1) acc -> D (fp32 overlay on H region)
#pragma unroll
                for (int i = 0; i < 4; i++) {
                    int o = ob + i * 16 + (lane >> 2);
#pragma unroll
                    for (int j = 0; j < 4; j++) {
                        int n = nb + j * 8 + 2 * (lane & 3);
                        sts_f32(d_addr(hb, n, o),     acc[i][j][0]);
                        sts_f32(d_addr(hb, n + 1, o), acc[i][j][1]);
                        sts_f32(d_addr(hb, n, o + 8),     acc[i][j][2]);
                        sts_f32(d_addr(hb, n + 1, o + 8), acc[i][j][3]);
                    }
                }
                __syncthreads();
                // 2) each thread: channel o = tid&255, samples shalf..shalf+1
                const int o = tid & 255;
                const int shalf = (tid >> 8) * 2;
                ull du[2][13];
#pragma unroll
                for (int q = 0; q < 2; q++) {
                    int s = shalf + q;
                    float tv[26];
                    tv[25] = 0.f;
#pragma unroll
                    for (int u = 0; u < 25; u++)
                        tv[u] = lds_f32(d_addr(hb, s * 32 + u, o));
#pragma unroll
                    for (int j = 0; j < 13; j++)
                        du[q][j] = (ull)__float_as_uint(tv[2 * j])
                                 | ((ull)__float_as_uint(tv[2 * j + 1]) << 32);
                }
                __syncthreads();
                // 3) A^T mult + bias + lrelu + re-split into H (v-outer: A
                //    row loaded once, reused for both samples)
                float bb = lds_f32(base + BIAS_OFF + (l * 256 + o) * 4);
#pragma unroll 5
                for (int v = 0; v < VDIM; v++) {
                    ull ar[13];
#pragma unroll
                    for (int j = 0; j < 13; j++)
                        ar[j] = lds_u64(base + AS2_OFF + (v * 13 + j) * 8);
#pragma unroll
                    for (int q = 0; q < 2; q++) {
                        ull accv = 0ull;
#pragma unroll
                        for (int j = 0; j < 13; j++)
                            accv = fma2(du[q][j], ar[j], accv);
                        float a0, a1;
                        asm("mov.b64 {%0,%1}, %2;" : "=f"(a0), "=f"(a1) : "l"(accv));
                        float r = a0 + a1 + bb;
                        r = (r >= 0.f) ? r : NEG_SLOPE * r;
                        uint16_t hi, lo;
                        split2(r, hi, lo);
                        int nr = (shalf + q) * 32 + v;
                        sts_u16(h_addr(hb, nr, o), hi);
                        sts_u16(h_addr(hb, nr, 256 + o), lo);
                    }
                }
                __syncthreads();
            } else {
                // final layer: bias + direct gmem store from fragments
#pragma unroll
                for (int i = 0; i < 4; i++) {
                    int o0 = ob + i * 16 + (lane >> 2);
                    float bb0 = lds_f32(base + BIAS_OFF + (512 + o0) * 4);
                    float bb1 = lds_f32(base + BIAS_OFF + (512 + o0 + 8) * 4);
#pragma unroll
                    for (int j = 0; j < 4; j++) {
                        int n = nb + j * 8 + 2 * (lane & 3);
                        int s = n >> 5, v = n & 31;
                        size_t o_base = ((size_t)(blk * NSAMP + s)) * (CDIM * VDIM);
                        if (v < VDIM) {
                            out[o_base + o0 * VDIM + v] = acc[i][j][0] + bb0;
                            out[o_base + (o0 + 8) * VDIM + v] = acc[i][j][2] + bb1;
                        }
                        if (v + 1 < VDIM) {
                            out[o_base + o0 * VDIM + v + 1] = acc[i][j][1] + bb0;
                            out[o_base + (o0 + 8) * VDIM + v + 1] = acc[i][j][3] + bb1;
                        }
                    }
                }
            }
            // reset accumulators for next layer
#pragma unroll
            for (int i = 0; i < 4; i++)
#pragma unroll
                for (int j = 0; j < 4; j++)
#pragma unroll
                    for (int e = 0; e < 4; e++) acc[i][j][e] = 0.f;
        }
    }
}

// ---------------------------------------------------------------------------
extern "C" void kernel_launch(void* const* d_in, const int* in_sizes, int n_in,
                              void* d_out, int out_size) {
    const float* x  = (const float*)d_in[0];
    const float* A  = (const float*)d_in[1];
    const float* w1 = (const float*)d_in[2];
    const float* b1 = (const float*)d_in[3];
    const float* w2 = (const float*)d_in[4];
    const float* b2 = (const float*)d_in[5];
    const float* wp = (const float*)d_in[6];
    const float* bp = (const float*)d_in[7];
    const int*   t  = (const int*)d_in[8];
    float* out = (float*)d_out;

    const int B = in_sizes[0] / (CDIM * VDIM);   // 4096

    cudaFuncSetAttribute(ode_main, cudaFuncAttributeMaxDynamicSharedMemorySize,
                         SMEM_DYN);

    pe_init_kernel<<<(PE_LEN * CDIM + 255) / 256, 256>>>();
    w_split_kernel<<<(3 * CDIM * CDIM + 255) / 256, 256>>>(w1, w2, wp);
    ode_main<<<B / NSAMP, 512, SMEM_DYN>>>(x, A, b1, b2, bp, t, out);
}